// round 2
// baseline (speedup 1.0000x reference)
#include <cuda_runtime.h>

#define BB 2
#define HH 128
#define WW 128
#define CC 128
#define NBR 9
#define TILE_P 16
#define NEDGE (TILE_P*NBR)   /* 144 */
#define NTHREADS 256

// ---------------- device scratch (no cudaMalloc allowed) ----------------
__device__ float g_norm[BB*HH*WW*CC];              // 16 MB LN1 output
__device__ float g_Ud[CC*CC], g_Vd[CC*CC];         // folded drive-MLP weights
__device__ float g_Ur[CC*CC], g_Vr[CC*CC];         // folded res-MLP weights
__device__ float g_biasd[NBR*CC], g_biasr[NBR*CC]; // per-neighbor bias (rel_pos folded)

// ---------------- helpers ----------------
__device__ __forceinline__ float2 ffma2(float2 a, float2 b, float2 c) {
    unsigned long long au = *reinterpret_cast<unsigned long long*>(&a);
    unsigned long long bu = *reinterpret_cast<unsigned long long*>(&b);
    unsigned long long cu = *reinterpret_cast<unsigned long long*>(&c);
    unsigned long long du;
    asm("fma.rn.f32x2 %0, %1, %2, %3;" : "=l"(du) : "l"(au), "l"(bu), "l"(cu));
    return *reinterpret_cast<float2*>(&du);
}

__device__ __forceinline__ float gelu_exact(float x) {
    return 0.5f * x * (1.0f + erff(x * 0.70710678118654752f));
}

// ---------------- prep: fold dW1/rW1 + rel_pos into U/V/bias ----------------
__global__ void prep_kernel(const float* __restrict__ dW1, const float* __restrict__ db1,
                            const float* __restrict__ rW1, const float* __restrict__ rb1,
                            const float* __restrict__ rel_pos) {
    int idx = blockIdx.x * blockDim.x + threadIdx.x;
    if (idx < CC*CC) {
        int c = idx >> 7, j = idx & 127;
        g_Ud[idx] = dW1[c*CC + j]       + dW1[(256 + c)*CC + j];
        g_Vd[idx] = dW1[(128 + c)*CC+j] - dW1[(256 + c)*CC + j];
        g_Ur[idx] = rW1[c*CC + j]       + rW1[(256 + c)*CC + j];
        g_Vr[idx] = rW1[(128 + c)*CC+j] - rW1[(256 + c)*CC + j];
    }
    if (idx < NBR*CC) {
        int n = idx >> 7, j = idx & 127;
        float bd = db1[j], br = rb1[j];
        #pragma unroll
        for (int r = 0; r < 8; ++r) {
            float rp = rel_pos[n*8 + r];
            bd += rp * dW1[(384 + r)*CC + j];
            br += rp * rW1[(384 + r)*CC + j];
        }
        g_biasd[idx] = bd;
        g_biasr[idx] = br;
    }
}

// ---------------- LN1 ----------------
__global__ void ln1_kernel(const float* __restrict__ tokens,
                           const float* __restrict__ g, const float* __restrict__ b) {
    int warp = threadIdx.x >> 5, lane = threadIdx.x & 31;
    int row  = blockIdx.x * 8 + warp;
    float4 x = reinterpret_cast<const float4*>(tokens + (long)row*CC)[lane];
    float s = x.x + x.y + x.z + x.w;
    #pragma unroll
    for (int o = 16; o; o >>= 1) s += __shfl_xor_sync(0xffffffffu, s, o);
    float m = s * (1.0f/128.0f);
    float dx = x.x - m, dy = x.y - m, dz = x.z - m, dw = x.w - m;
    float v = dx*dx + dy*dy + dz*dz + dw*dw;
    #pragma unroll
    for (int o = 16; o; o >>= 1) v += __shfl_xor_sync(0xffffffffu, v, o);
    float rs = rsqrtf(v * (1.0f/128.0f) + 1e-5f);
    int c = lane * 4;
    float4 o4;
    o4.x = dx*rs*g[c+0] + b[c+0];
    o4.y = dy*rs*g[c+1] + b[c+1];
    o4.z = dz*rs*g[c+2] + b[c+2];
    o4.w = dw*rs*g[c+3] + b[c+3];
    reinterpret_cast<float4*>(g_norm + (long)row*CC)[lane] = o4;
}

// ---------------- fused main kernel: one CTA = 16 positions ----------------
__global__ __launch_bounds__(NTHREADS, 2)
void eml_main_kernel(const float* __restrict__ tokens,
                     const float* __restrict__ ln2_g, const float* __restrict__ ln2_b,
                     const float* __restrict__ dW2, const float* __restrict__ db2,
                     const float* __restrict__ rW2, const float* __restrict__ rb2,
                     const float* __restrict__ vW,  const float* __restrict__ vb,
                     const float* __restrict__ oW,  const float* __restrict__ ob,
                     const float* __restrict__ p_gamma, const float* __restrict__ p_lam,
                     const float* __restrict__ p_bias,
                     float* __restrict__ out) {
    extern __shared__ float sm[];
    float* nbS    = sm;                       // [144][128] scrambled nbhd tile
    float* cuS    = nbS    + NEDGE*CC;        // [16][256] center@(Ud|Ur)
    float* biasS  = cuS    + TILE_P*256;      // [9][256]
    float* cenS   = biasS  + NBR*256;         // [16][128] centers (reused as wsS)
    float* driveS = cenS   + TILE_P*CC;       // [144]
    float* resS   = driveS + NEDGE;           // [144]
    float* gateS  = resS   + NEDGE;           // [144]
    float* invmS  = gateS  + NEDGE;           // [16]
    float* sgS    = invmS  + TILE_P;          // [16]
    float* wsS  = cenS;    // reuse (cen dead after cu phase)
    float* msgS = cuS;     // reuse (cu dead after GEMM)
    float* uS   = nbS;     // reuse (nb dead after weighted sum)

    const int tid = threadIdx.x;
    const int blk = blockIdx.x;
    const int b   = blk >> 10;            // / (128*8)
    const int t   = blk & 1023;
    const int h   = t >> 3;
    const int w0  = (t & 7) << 4;
    const int rowbase = (b*HH + h)*WW + w0;   // flat position index of p=0

    // --- stage bias table [9][256] ---
    for (int idx = tid; idx < NBR*256; idx += NTHREADS) {
        int n = idx >> 8, j = idx & 255;
        biasS[idx] = (j < 128) ? g_biasd[n*CC + j] : g_biasr[n*CC + j - 128];
    }
    // --- stage centers [16][128] (contiguous rows) ---
    for (int idx = tid; idx < TILE_P*CC; idx += NTHREADS)
        cenS[idx] = g_norm[(long)rowbase*CC + idx];
    // --- gather scrambled nbhd: nbhd[p,n,c] = padnorm[shift s][c'], f=n*128+c, c'=f/9, s=f%9 ---
    for (int idx = tid; idx < NEDGE*CC; idx += NTHREADS) {
        int e = idx >> 7, c = idx & 127;
        int p = e / 9;
        int n = e - p*9;
        int f = n*128 + c;
        int c2 = f / 9;
        int s  = f - c2*9;
        int di = s / 3;
        int dj = s - di*3;
        int hh = h + di - 1;
        int ww = w0 + p + dj - 1;
        float val = 0.0f;
        if ((unsigned)hh < HH && (unsigned)ww < WW)
            val = g_norm[(((long)(b*HH + hh)*WW + ww))*CC + c2];
        nbS[idx] = val;
    }
    __syncthreads();

    // --- cu = center @ [Ud|Ur]  (f32x2 packed) ---
    {
        int jp = tid & 127;           // column pair (2jp, 2jp+1) of 256
        int ph = tid >> 7;            // p-half
        const float* Up = (jp < 64) ? (g_Ud + 2*jp) : (g_Ur + (2*jp - 128));
        for (int p = ph*8; p < ph*8 + 8; ++p) {
            float2 acc = make_float2(0.f, 0.f);
            const float* cen = cenS + p*CC;
            #pragma unroll 8
            for (int c = 0; c < CC; ++c) {
                float cv = cen[c];
                float2 u2 = *reinterpret_cast<const float2*>(Up + c*CC);
                acc = ffma2(make_float2(cv, cv), u2, acc);
            }
            *reinterpret_cast<float2*>(cuS + p*256 + 2*jp) = acc;
        }
    }
    __syncthreads();

    // --- edge GEMM: H[e][j2] = gelu(cu + nbhd@V + bias), then dot W2 -> drive/res ---
    const int jq   = tid & 63;                 // 64 column-groups of 4
    const int eq   = tid >> 6;                 // 4 position groups
    const int j2b  = jq * 4;
    const bool isDrive = (jq < 32);
    const float* Vp  = isDrive ? (g_Vd + j2b) : (g_Vr + (j2b - 128));
    const float* W2p = isDrive ? dW2 : rW2;
    const int wcol = isDrive ? j2b : (j2b - 128);
    const float w2_0 = W2p[wcol+0], w2_1 = W2p[wcol+1], w2_2 = W2p[wcol+2], w2_3 = W2p[wcol+3];
    const int lane = tid & 31;

    for (int ck = 0; ck < 4; ++ck) {
        const int p = ck*4 + eq;               // each chunk: this thread's 9 edges of position p
        float2 alo[9], ahi[9];
        float4 cu4 = *reinterpret_cast<const float4*>(cuS + p*256 + j2b);
        #pragma unroll
        for (int i = 0; i < 9; ++i) {
            float4 b4 = *reinterpret_cast<const float4*>(biasS + i*256 + j2b);
            alo[i] = make_float2(cu4.x + b4.x, cu4.y + b4.y);
            ahi[i] = make_float2(cu4.z + b4.z, cu4.w + b4.w);
        }
        const float* nbp = nbS + p*9*CC;
        #pragma unroll 4
        for (int c = 0; c < CC; ++c) {
            float4 v = *reinterpret_cast<const float4*>(Vp + c*CC);
            float2 vlo = make_float2(v.x, v.y);
            float2 vhi = make_float2(v.z, v.w);
            #pragma unroll
            for (int i = 0; i < 9; ++i) {
                float nbv = nbp[i*CC + c];          // smem broadcast across warp
                float2 nb2 = make_float2(nbv, nbv);
                alo[i] = ffma2(nb2, vlo, alo[i]);
                ahi[i] = ffma2(nb2, vhi, ahi[i]);
            }
        }
        #pragma unroll
        for (int i = 0; i < 9; ++i) {
            float partial = gelu_exact(alo[i].x)*w2_0 + gelu_exact(alo[i].y)*w2_1
                          + gelu_exact(ahi[i].x)*w2_2 + gelu_exact(ahi[i].y)*w2_3;
            #pragma unroll
            for (int o = 16; o; o >>= 1)
                partial += __shfl_xor_sync(0xffffffffu, partial, o);
            if (lane == 0)
                (isDrive ? driveS : resS)[p*9 + i] = partial;
        }
    }
    __syncthreads();

    // --- EML gate ---
    const float gamma = *p_gamma, lam = *p_lam, ebias = *p_bias;
    if (tid < NEDGE) {
        float d = driveS[tid] + db2[0];
        float r = resS[tid]   + rb2[0];
        float sp = fmaxf(r, 0.0f) + log1pf(expf(-fabsf(r)));   // jax softplus
        float en = gamma * d / (lam * sp + 1e-6f) + ebias;
        en = fminf(fmaxf(en, -3.0f), 3.0f);
        gateS[tid] = 1.0f / (1.0f + expf(-en));
    }
    __syncthreads();
    if (tid < TILE_P) {
        float s = 0.0f;
        #pragma unroll
        for (int n = 0; n < 9; ++n) s += gateS[tid*9 + n];
        sgS[tid]   = s;
        invmS[tid] = 1.0f / fmaxf(s, 1e-6f);
    }
    __syncthreads();

    // --- ws[p][c] = (sum_n gate*nbhd)/mass ---
    {
        int p = tid >> 4, cg = tid & 15;
        float im = invmS[p];
        float gr[9];
        #pragma unroll
        for (int n = 0; n < 9; ++n) gr[n] = gateS[p*9 + n];
        #pragma unroll
        for (int k = 0; k < 8; ++k) {
            int c = cg + (k << 4);
            float s = 0.0f;
            #pragma unroll
            for (int n = 0; n < 9; ++n) s += gr[n] * nbS[(p*9 + n)*CC + c];
            wsS[p*CC + c] = s * im;
        }
    }
    __syncthreads();

    // --- message = ws @ vW + vb*(sum_gate/mass) ---
    {
        int p = tid >> 4, dg = tid & 15;
        float coef = sgS[p] * invmS[p];
        #pragma unroll
        for (int k = 0; k < 8; ++k) {
            int d = dg + (k << 4);
            float s = 0.0f;
            #pragma unroll 8
            for (int c = 0; c < CC; ++c) s += wsS[p*CC + c] * vW[c*CC + d];
            msgS[p*CC + d] = s + vb[d] * coef;
        }
    }
    __syncthreads();

    // --- u = tokens + message @ oW + ob ---
    {
        int p = tid >> 4, dg = tid & 15;
        long grow = (long)(rowbase + p) * CC;
        #pragma unroll
        for (int k = 0; k < 8; ++k) {
            int d2 = dg + (k << 4);
            float s = 0.0f;
            #pragma unroll 8
            for (int d = 0; d < CC; ++d) s += msgS[p*CC + d] * oW[d*CC + d2];
            uS[p*CC + d2] = tokens[grow + d2] + s + ob[d2];
        }
    }
    __syncthreads();

    // --- LN2 + store ---
    {
        int warp = tid >> 5, lanei = tid & 31;
        #pragma unroll
        for (int pp = 0; pp < 2; ++pp) {
            int p = warp*2 + pp;
            float4 x = reinterpret_cast<const float4*>(uS + p*CC)[lanei];
            float s = x.x + x.y + x.z + x.w;
            #pragma unroll
            for (int o = 16; o; o >>= 1) s += __shfl_xor_sync(0xffffffffu, s, o);
            float m = s * (1.0f/128.0f);
            float dx = x.x - m, dy = x.y - m, dz = x.z - m, dw = x.w - m;
            float v = dx*dx + dy*dy + dz*dz + dw*dw;
            #pragma unroll
            for (int o = 16; o; o >>= 1) v += __shfl_xor_sync(0xffffffffu, v, o);
            float rs = rsqrtf(v * (1.0f/128.0f) + 1e-5f);
            int c = lanei * 4;
            float4 o4;
            o4.x = dx*rs*ln2_g[c+0] + ln2_b[c+0];
            o4.y = dy*rs*ln2_g[c+1] + ln2_b[c+1];
            o4.z = dz*rs*ln2_g[c+2] + ln2_b[c+2];
            o4.w = dw*rs*ln2_g[c+3] + ln2_b[c+3];
            reinterpret_cast<float4*>(out + (long)(rowbase + p)*CC)[lanei] = o4;
        }
    }
}

// ---------------- launch ----------------
extern "C" void kernel_launch(void* const* d_in, const int* in_sizes, int n_in,
                              void* d_out, int out_size) {
    const float* tokens = (const float*)d_in[0];
    const float* ln1_g  = (const float*)d_in[1];
    const float* ln1_b  = (const float*)d_in[2];
    const float* ln2_g  = (const float*)d_in[3];
    const float* ln2_b  = (const float*)d_in[4];
    const float* rel_pos= (const float*)d_in[5];
    const float* dW1    = (const float*)d_in[6];
    const float* db1    = (const float*)d_in[7];
    const float* dW2    = (const float*)d_in[8];
    const float* db2    = (const float*)d_in[9];
    const float* rW1    = (const float*)d_in[10];
    const float* rb1    = (const float*)d_in[11];
    const float* rW2    = (const float*)d_in[12];
    const float* rb2    = (const float*)d_in[13];
    const float* vW     = (const float*)d_in[14];
    const float* vb     = (const float*)d_in[15];
    const float* oW     = (const float*)d_in[16];
    const float* ob     = (const float*)d_in[17];
    const float* gamma  = (const float*)d_in[18];
    const float* lam    = (const float*)d_in[19];
    const float* ebias  = (const float*)d_in[20];
    float* out = (float*)d_out;

    const int SMEM = (NEDGE*CC + TILE_P*256 + NBR*256 + TILE_P*CC + NEDGE*3 + TILE_P*2) * 4;

    prep_kernel<<<64, 256>>>(dW1, db1, rW1, rb1, rel_pos);
    ln1_kernel<<<(BB*HH*WW)/8, 256>>>(tokens, ln1_g, ln1_b);   // 4096 blocks x 8 rows
    cudaFuncSetAttribute(eml_main_kernel, cudaFuncAttributeMaxDynamicSharedMemorySize, SMEM);
    eml_main_kernel<<<(BB*HH*WW)/TILE_P, 256, SMEM>>>(tokens, ln2_g, ln2_b, dW2, db2,
                                                      rW2, rb2, vW, vb, oW, ob,
                                                      gamma, lam, ebias, out);
}

// round 4
// speedup vs baseline: 1.1443x; 1.1443x over previous
#include <cuda_runtime.h>

#define BB 2
#define HH 128
#define WW 128
#define CC 128
#define NBR 9
#define TILE_P 16
#define NEDGE (TILE_P*NBR)   /* 144 */
#define NTHREADS 256

// ---------------- device scratch (no cudaMalloc allowed) ----------------
__device__ float g_norm[BB*HH*WW*CC];              // 16 MB LN1 output
__device__ float g_Ud[CC*CC], g_Vd[CC*CC];         // folded drive-MLP weights
__device__ float g_Ur[CC*CC], g_Vr[CC*CC];         // folded res-MLP weights
__device__ float g_biasd[NBR*CC], g_biasr[NBR*CC]; // per-neighbor bias (rel_pos folded)

// ---------------- helpers ----------------
__device__ __forceinline__ float2 ffma2(float2 a, float2 b, float2 c) {
    unsigned long long au = *reinterpret_cast<unsigned long long*>(&a);
    unsigned long long bu = *reinterpret_cast<unsigned long long*>(&b);
    unsigned long long cu = *reinterpret_cast<unsigned long long*>(&c);
    unsigned long long du;
    asm("fma.rn.f32x2 %0, %1, %2, %3;" : "=l"(du) : "l"(au), "l"(bu), "l"(cu));
    return *reinterpret_cast<float2*>(&du);
}

__device__ __forceinline__ float gelu_exact(float x) {
    return 0.5f * x * (1.0f + erff(x * 0.70710678118654752f));
}

// ---------------- setup: prep (fold weights) + LN1, merged ----------------
__global__ void setup_kernel(const float* __restrict__ tokens,
                             const float* __restrict__ g, const float* __restrict__ b,
                             const float* __restrict__ dW1, const float* __restrict__ db1,
                             const float* __restrict__ rW1, const float* __restrict__ rb1,
                             const float* __restrict__ rel_pos) {
    if (blockIdx.x < 4096) {
        // --- LN1: 8 rows per block ---
        int warp = threadIdx.x >> 5, lane = threadIdx.x & 31;
        int row  = blockIdx.x * 8 + warp;
        float4 x = reinterpret_cast<const float4*>(tokens + (long)row*CC)[lane];
        float s = x.x + x.y + x.z + x.w;
        #pragma unroll
        for (int o = 16; o; o >>= 1) s += __shfl_xor_sync(0xffffffffu, s, o);
        float m = s * (1.0f/128.0f);
        float dx = x.x - m, dy = x.y - m, dz = x.z - m, dw = x.w - m;
        float v = dx*dx + dy*dy + dz*dz + dw*dw;
        #pragma unroll
        for (int o = 16; o; o >>= 1) v += __shfl_xor_sync(0xffffffffu, v, o);
        float rs = rsqrtf(v * (1.0f/128.0f) + 1e-5f);
        int c = lane * 4;
        float4 o4;
        o4.x = dx*rs*g[c+0] + b[c+0];
        o4.y = dy*rs*g[c+1] + b[c+1];
        o4.z = dz*rs*g[c+2] + b[c+2];
        o4.w = dw*rs*g[c+3] + b[c+3];
        reinterpret_cast<float4*>(g_norm + (long)row*CC)[lane] = o4;
    } else {
        // --- prep: fold dW1/rW1 + rel_pos into U/V/bias ---
        int idx = (blockIdx.x - 4096) * blockDim.x + threadIdx.x;
        if (idx < CC*CC) {
            int c = idx >> 7, j = idx & 127;
            g_Ud[idx] = dW1[c*CC + j]       + dW1[(256 + c)*CC + j];
            g_Vd[idx] = dW1[(128 + c)*CC+j] - dW1[(256 + c)*CC + j];
            g_Ur[idx] = rW1[c*CC + j]       + rW1[(256 + c)*CC + j];
            g_Vr[idx] = rW1[(128 + c)*CC+j] - rW1[(256 + c)*CC + j];
        }
        if (idx < NBR*CC) {
            int n = idx >> 7, j = idx & 127;
            float bd = db1[j], br = rb1[j];
            #pragma unroll
            for (int r = 0; r < 8; ++r) {
                float rp = rel_pos[n*8 + r];
                bd += rp * dW1[(384 + r)*CC + j];
                br += rp * rW1[(384 + r)*CC + j];
            }
            g_biasd[idx] = bd;
            g_biasr[idx] = br;
        }
    }
}

// ---------------- fused main kernel: one CTA = 16 positions ----------------
__global__ __launch_bounds__(NTHREADS, 2)
void eml_main_kernel(const float* __restrict__ tokens,
                     const float* __restrict__ ln2_g, const float* __restrict__ ln2_b,
                     const float* __restrict__ dW2, const float* __restrict__ db2,
                     const float* __restrict__ rW2, const float* __restrict__ rb2,
                     const float* __restrict__ vW,  const float* __restrict__ vb,
                     const float* __restrict__ oW,  const float* __restrict__ ob,
                     const float* __restrict__ p_gamma, const float* __restrict__ p_lam,
                     const float* __restrict__ p_bias,
                     float* __restrict__ out) {
    extern __shared__ float sm[];
    float* nbS    = sm;                       // [144][128] scrambled nbhd tile
    float* cuS    = nbS    + NEDGE*CC;        // [16][256] center@(Ud|Ur)
    float* biasS  = cuS    + TILE_P*256;      // [9][256]
    float* cenS   = biasS  + NBR*256;         // [16][128] centers (reused as wsS)
    float* driveS = cenS   + TILE_P*CC;       // [144]
    float* resS   = driveS + NEDGE;           // [144]
    float* gateS  = resS   + NEDGE;           // [144]
    float* invmS  = gateS  + NEDGE;           // [16]
    float* sgS    = invmS  + TILE_P;          // [16]
    float* wsS  = cenS;    // reuse (cen dead after cu phase)
    float* msgS = cuS;     // reuse (cu dead after GEMM)
    float* uS   = nbS;     // reuse (nb dead after weighted sum)

    const int tid = threadIdx.x;
    const int blk = blockIdx.x;
    const int b   = blk >> 10;
    const int t   = blk & 1023;
    const int h   = t >> 3;
    const int w0  = (t & 7) << 4;
    const int rowbase = (b*HH + h)*WW + w0;   // flat position index of p=0

    // --- stage bias table [9][256] ---
    for (int idx = tid; idx < NBR*256; idx += NTHREADS) {
        int n = idx >> 8, j = idx & 255;
        biasS[idx] = (j < 128) ? g_biasd[n*CC + j] : g_biasr[n*CC + j - 128];
    }
    // --- stage centers [16][128] ---
    for (int idx = tid; idx < TILE_P*CC; idx += NTHREADS)
        cenS[idx] = g_norm[(long)rowbase*CC + idx];
    // --- gather scrambled nbhd: nbhd[p,n,c] = padnorm[shift s][c'], f=n*128+c, c'=f/9, s=f%9 ---
    for (int idx = tid; idx < NEDGE*CC; idx += NTHREADS) {
        int e = idx >> 7, c = idx & 127;
        int p = e / 9;
        int n = e - p*9;
        int f = n*128 + c;
        int c2 = f / 9;
        int s  = f - c2*9;
        int di = s / 3;
        int dj = s - di*3;
        int hh = h + di - 1;
        int ww = w0 + p + dj - 1;
        float val = 0.0f;
        if ((unsigned)hh < HH && (unsigned)ww < WW)
            val = g_norm[(((long)(b*HH + hh)*WW + ww))*CC + c2];
        nbS[idx] = val;
    }
    __syncthreads();

    // --- cu = center @ [Ud|Ur]  (f32x2 packed) ---
    {
        int jp = tid & 127;           // column pair (2jp, 2jp+1) of 256
        int ph = tid >> 7;            // p-half
        const float* Up = (jp < 64) ? (g_Ud + 2*jp) : (g_Ur + (2*jp - 128));
        for (int p = ph*8; p < ph*8 + 8; ++p) {
            float2 acc = make_float2(0.f, 0.f);
            const float* cen = cenS + p*CC;
            #pragma unroll 8
            for (int c = 0; c < CC; ++c) {
                float cv = cen[c];
                float2 u2 = *reinterpret_cast<const float2*>(Up + c*CC);
                acc = ffma2(make_float2(cv, cv), u2, acc);
            }
            *reinterpret_cast<float2*>(cuS + p*256 + 2*jp) = acc;
        }
    }
    __syncthreads();

    // --- edge GEMM: H[e][j2] = gelu(cu + nbhd@V + bias), then dot W2 -> drive/res ---
    const int jq   = tid & 63;                 // 64 column-groups of 4
    const int eq   = tid >> 6;                 // 4 position groups
    const int j2b  = jq * 4;
    const bool isDrive = (jq < 32);
    const float* Vp  = isDrive ? (g_Vd + j2b) : (g_Vr + (j2b - 128));
    const float* W2p = isDrive ? dW2 : rW2;
    const int wcol = isDrive ? j2b : (j2b - 128);
    const float w2_0 = W2p[wcol+0], w2_1 = W2p[wcol+1], w2_2 = W2p[wcol+2], w2_3 = W2p[wcol+3];
    const int lane = tid & 31;

    for (int ck = 0; ck < 4; ++ck) {
        const int p = ck*4 + eq;               // this thread's 9 edges of position p
        float2 alo[9], ahi[9];
        float4 cu4 = *reinterpret_cast<const float4*>(cuS + p*256 + j2b);
        #pragma unroll
        for (int i = 0; i < 9; ++i) {
            float4 b4 = *reinterpret_cast<const float4*>(biasS + i*256 + j2b);
            alo[i] = make_float2(cu4.x + b4.x, cu4.y + b4.y);
            ahi[i] = make_float2(cu4.z + b4.z, cu4.w + b4.w);
        }
        const float* nbp = nbS + p*9*CC;
        // quad-blocked K loop: LDS.128 per edge per 4 c's (LSU wavefronts /4)
        for (int c0 = 0; c0 < CC; c0 += 4) {
            float4 nbq[9];
            #pragma unroll
            for (int i = 0; i < 9; ++i)
                nbq[i] = *reinterpret_cast<const float4*>(nbp + i*CC + c0);
            #pragma unroll
            for (int cc = 0; cc < 4; ++cc) {
                float4 v = *reinterpret_cast<const float4*>(Vp + (c0 + cc)*CC);
                float2 vlo = make_float2(v.x, v.y);
                float2 vhi = make_float2(v.z, v.w);
                #pragma unroll
                for (int i = 0; i < 9; ++i) {
                    float nbv = (cc == 0) ? nbq[i].x : (cc == 1) ? nbq[i].y
                              : (cc == 2) ? nbq[i].z : nbq[i].w;
                    float2 nb2 = make_float2(nbv, nbv);
                    alo[i] = ffma2(nb2, vlo, alo[i]);
                    ahi[i] = ffma2(nb2, vhi, ahi[i]);
                }
            }
        }
        #pragma unroll
        for (int i = 0; i < 9; ++i) {
            float partial = gelu_exact(alo[i].x)*w2_0 + gelu_exact(alo[i].y)*w2_1
                          + gelu_exact(ahi[i].x)*w2_2 + gelu_exact(ahi[i].y)*w2_3;
            #pragma unroll
            for (int o = 16; o; o >>= 1)
                partial += __shfl_xor_sync(0xffffffffu, partial, o);
            if (lane == 0)
                (isDrive ? driveS : resS)[p*9 + i] = partial;
        }
    }
    __syncthreads();

    // --- EML gate ---
    const float gamma = *p_gamma, lam = *p_lam, ebias = *p_bias;
    if (tid < NEDGE) {
        float d = driveS[tid] + db2[0];
        float r = resS[tid]   + rb2[0];
        float sp = fmaxf(r, 0.0f) + log1pf(expf(-fabsf(r)));   // jax softplus
        float en = gamma * d / (lam * sp + 1e-6f) + ebias;
        en = fminf(fmaxf(en, -3.0f), 3.0f);
        gateS[tid] = 1.0f / (1.0f + expf(-en));
    }
    __syncthreads();
    if (tid < TILE_P) {
        float s = 0.0f;
        #pragma unroll
        for (int n = 0; n < 9; ++n) s += gateS[tid*9 + n];
        sgS[tid]   = s;
        invmS[tid] = 1.0f / fmaxf(s, 1e-6f);
    }
    __syncthreads();

    // --- ws[p][c] = (sum_n gate*nbhd)/mass ---
    {
        int p = tid >> 4, cg = tid & 15;
        float im = invmS[p];
        float gr[9];
        #pragma unroll
        for (int n = 0; n < 9; ++n) gr[n] = gateS[p*9 + n];
        #pragma unroll
        for (int k = 0; k < 8; ++k) {
            int c = cg + (k << 4);
            float s = 0.0f;
            #pragma unroll
            for (int n = 0; n < 9; ++n) s += gr[n] * nbS[(p*9 + n)*CC + c];
            wsS[p*CC + c] = s * im;
        }
    }
    __syncthreads();

    // --- message = ws @ vW + vb*(sum_gate/mass)   (c-outer, contiguous d, packed) ---
    {
        int p = tid >> 4, dg = tid & 15;
        int d0 = dg * 8;                        // thread owns d in [d0, d0+8)
        float coef = sgS[p] * invmS[p];
        float2 acc[4] = {{0,0},{0,0},{0,0},{0,0}};
        const float* wsp = wsS + p*CC;
        #pragma unroll 4
        for (int c = 0; c < CC; ++c) {
            float w = wsp[c];                   // broadcast LDS
            float2 w2 = make_float2(w, w);
            const float4* vr = reinterpret_cast<const float4*>(vW + c*CC + d0);
            float4 v0 = vr[0], v1 = vr[1];
            acc[0] = ffma2(w2, make_float2(v0.x, v0.y), acc[0]);
            acc[1] = ffma2(w2, make_float2(v0.z, v0.w), acc[1]);
            acc[2] = ffma2(w2, make_float2(v1.x, v1.y), acc[2]);
            acc[3] = ffma2(w2, make_float2(v1.z, v1.w), acc[3]);
        }
        #pragma unroll
        for (int k = 0; k < 4; ++k) {
            msgS[p*CC + d0 + 2*k]     = acc[k].x + vb[d0 + 2*k]     * coef;
            msgS[p*CC + d0 + 2*k + 1] = acc[k].y + vb[d0 + 2*k + 1] * coef;
        }
    }
    __syncthreads();

    // --- u = tokens + message @ oW + ob   (same structure) ---
    {
        int p = tid >> 4, dg = tid & 15;
        int d0 = dg * 8;
        long grow = (long)(rowbase + p) * CC;
        float2 acc[4] = {{0,0},{0,0},{0,0},{0,0}};
        const float* mp = msgS + p*CC;
        #pragma unroll 4
        for (int c = 0; c < CC; ++c) {
            float w = mp[c];
            float2 w2 = make_float2(w, w);
            const float4* orr = reinterpret_cast<const float4*>(oW + c*CC + d0);
            float4 v0 = orr[0], v1 = orr[1];
            acc[0] = ffma2(w2, make_float2(v0.x, v0.y), acc[0]);
            acc[1] = ffma2(w2, make_float2(v0.z, v0.w), acc[1]);
            acc[2] = ffma2(w2, make_float2(v1.x, v1.y), acc[2]);
            acc[3] = ffma2(w2, make_float2(v1.z, v1.w), acc[3]);
        }
        __syncthreads();   // msgS fully consumed before uS (aliases nbS, distinct) -- safe ordering for reuse
        #pragma unroll
        for (int k = 0; k < 4; ++k) {
            int d2 = d0 + 2*k;
            uS[p*CC + d2]     = tokens[grow + d2]     + acc[k].x + ob[d2];
            uS[p*CC + d2 + 1] = tokens[grow + d2 + 1] + acc[k].y + ob[d2 + 1];
        }
    }
    __syncthreads();

    // --- LN2 + store ---
    {
        int warp = tid >> 5, lanei = tid & 31;
        #pragma unroll
        for (int pp = 0; pp < 2; ++pp) {
            int p = warp*2 + pp;
            float4 x = reinterpret_cast<const float4*>(uS + p*CC)[lanei];
            float s = x.x + x.y + x.z + x.w;
            #pragma unroll
            for (int o = 16; o; o >>= 1) s += __shfl_xor_sync(0xffffffffu, s, o);
            float m = s * (1.0f/128.0f);
            float dx = x.x - m, dy = x.y - m, dz = x.z - m, dw = x.w - m;
            float v = dx*dx + dy*dy + dz*dz + dw*dw;
            #pragma unroll
            for (int o = 16; o; o >>= 1) v += __shfl_xor_sync(0xffffffffu, v, o);
            float rs = rsqrtf(v * (1.0f/128.0f) + 1e-5f);
            int c = lanei * 4;
            float4 o4;
            o4.x = dx*rs*ln2_g[c+0] + ln2_b[c+0];
            o4.y = dy*rs*ln2_g[c+1] + ln2_b[c+1];
            o4.z = dz*rs*ln2_g[c+2] + ln2_b[c+2];
            o4.w = dw*rs*ln2_g[c+3] + ln2_b[c+3];
            reinterpret_cast<float4*>(out + (long)(rowbase + p)*CC)[lanei] = o4;
        }
    }
}

// ---------------- launch ----------------
extern "C" void kernel_launch(void* const* d_in, const int* in_sizes, int n_in,
                              void* d_out, int out_size) {
    const float* tokens = (const float*)d_in[0];
    const float* ln1_g  = (const float*)d_in[1];
    const float* ln1_b  = (const float*)d_in[2];
    const float* ln2_g  = (const float*)d_in[3];
    const float* ln2_b  = (const float*)d_in[4];
    const float* rel_pos= (const float*)d_in[5];
    const float* dW1    = (const float*)d_in[6];
    const float* db1    = (const float*)d_in[7];
    const float* dW2    = (const float*)d_in[8];
    const float* db2    = (const float*)d_in[9];
    const float* rW1    = (const float*)d_in[10];
    const float* rb1    = (const float*)d_in[11];
    const float* rW2    = (const float*)d_in[12];
    const float* rb2    = (const float*)d_in[13];
    const float* vW     = (const float*)d_in[14];
    const float* vb     = (const float*)d_in[15];
    const float* oW     = (const float*)d_in[16];
    const float* ob     = (const float*)d_in[17];
    const float* gamma  = (const float*)d_in[18];
    const float* lam    = (const float*)d_in[19];
    const float* ebias  = (const float*)d_in[20];
    float* out = (float*)d_out;

    const int SMEM = (NEDGE*CC + TILE_P*256 + NBR*256 + TILE_P*CC + NEDGE*3 + TILE_P*2) * 4;

    setup_kernel<<<4096 + 64, 256>>>(tokens, ln1_g, ln1_b, dW1, db1, rW1, rb1, rel_pos);
    cudaFuncSetAttribute(eml_main_kernel, cudaFuncAttributeMaxDynamicSharedMemorySize, SMEM);
    eml_main_kernel<<<(BB*HH*WW)/TILE_P, 256, SMEM>>>(tokens, ln2_g, ln2_b, dW2, db2,
                                                      rW2, rb2, vW, vb, oW, ob,
                                                      gamma, lam, ebias, out);
}

// round 5
// speedup vs baseline: 1.2199x; 1.0661x over previous
#include <cuda_runtime.h>

#define BB 2
#define HH 128
#define WW 128
#define CC 128
#define NBR 9
#define TILE_P 16
#define NEDGE (TILE_P*NBR)   /* 144 */
#define NTHREADS 256

// ---------------- device scratch (no cudaMalloc allowed) ----------------
__device__ float g_norm[BB*HH*WW*CC];              // 16 MB LN1 output
__device__ float g_Ud[CC*CC], g_Vd[CC*CC];         // folded drive-MLP weights
__device__ float g_Ur[CC*CC], g_Vr[CC*CC];         // folded res-MLP weights
__device__ float g_biasd[NBR*CC], g_biasr[NBR*CC]; // per-neighbor bias (rel_pos folded)

// ---------------- helpers ----------------
__device__ __forceinline__ float2 ffma2(float2 a, float2 b, float2 c) {
    unsigned long long au = *reinterpret_cast<unsigned long long*>(&a);
    unsigned long long bu = *reinterpret_cast<unsigned long long*>(&b);
    unsigned long long cu = *reinterpret_cast<unsigned long long*>(&c);
    unsigned long long du;
    asm("fma.rn.f32x2 %0, %1, %2, %3;" : "=l"(du) : "l"(au), "l"(bu), "l"(cu));
    return *reinterpret_cast<float2*>(&du);
}

__device__ __forceinline__ float gelu_exact(float x) {
    return 0.5f * x * (1.0f + erff(x * 0.70710678118654752f));
}

// ---------------- setup: prep (fold weights) + LN1, merged ----------------
__global__ void setup_kernel(const float* __restrict__ tokens,
                             const float* __restrict__ g, const float* __restrict__ b,
                             const float* __restrict__ dW1, const float* __restrict__ db1,
                             const float* __restrict__ rW1, const float* __restrict__ rb1,
                             const float* __restrict__ rel_pos) {
    if (blockIdx.x < 4096) {
        // --- LN1: 8 rows per block ---
        int warp = threadIdx.x >> 5, lane = threadIdx.x & 31;
        int row  = blockIdx.x * 8 + warp;
        float4 x = reinterpret_cast<const float4*>(tokens + (long)row*CC)[lane];
        float s = x.x + x.y + x.z + x.w;
        #pragma unroll
        for (int o = 16; o; o >>= 1) s += __shfl_xor_sync(0xffffffffu, s, o);
        float m = s * (1.0f/128.0f);
        float dx = x.x - m, dy = x.y - m, dz = x.z - m, dw = x.w - m;
        float v = dx*dx + dy*dy + dz*dz + dw*dw;
        #pragma unroll
        for (int o = 16; o; o >>= 1) v += __shfl_xor_sync(0xffffffffu, v, o);
        float rs = rsqrtf(v * (1.0f/128.0f) + 1e-5f);
        int c = lane * 4;
        float4 o4;
        o4.x = dx*rs*g[c+0] + b[c+0];
        o4.y = dy*rs*g[c+1] + b[c+1];
        o4.z = dz*rs*g[c+2] + b[c+2];
        o4.w = dw*rs*g[c+3] + b[c+3];
        reinterpret_cast<float4*>(g_norm + (long)row*CC)[lane] = o4;
    } else {
        // --- prep: fold dW1/rW1 + rel_pos into U/V/bias ---
        int idx = (blockIdx.x - 4096) * blockDim.x + threadIdx.x;
        if (idx < CC*CC) {
            int c = idx >> 7, j = idx & 127;
            g_Ud[idx] = dW1[c*CC + j]       + dW1[(256 + c)*CC + j];
            g_Vd[idx] = dW1[(128 + c)*CC+j] - dW1[(256 + c)*CC + j];
            g_Ur[idx] = rW1[c*CC + j]       + rW1[(256 + c)*CC + j];
            g_Vr[idx] = rW1[(128 + c)*CC+j] - rW1[(256 + c)*CC + j];
        }
        if (idx < NBR*CC) {
            int n = idx >> 7, j = idx & 127;
            float bd = db1[j], br = rb1[j];
            #pragma unroll
            for (int r = 0; r < 8; ++r) {
                float rp = rel_pos[n*8 + r];
                bd += rp * dW1[(384 + r)*CC + j];
                br += rp * rW1[(384 + r)*CC + j];
            }
            g_biasd[idx] = bd;
            g_biasr[idx] = br;
        }
    }
}

// ---------------- fused main kernel: one CTA = 16 positions ----------------
__global__ __launch_bounds__(NTHREADS, 2)
void eml_main_kernel(const float* __restrict__ tokens,
                     const float* __restrict__ ln2_g, const float* __restrict__ ln2_b,
                     const float* __restrict__ dW2, const float* __restrict__ db2,
                     const float* __restrict__ rW2, const float* __restrict__ rb2,
                     const float* __restrict__ vW,  const float* __restrict__ vb,
                     const float* __restrict__ oW,  const float* __restrict__ ob,
                     const float* __restrict__ p_gamma, const float* __restrict__ p_lam,
                     const float* __restrict__ p_bias,
                     float* __restrict__ out) {
    extern __shared__ float sm[];
    float* nbS    = sm;                       // [144][128] scrambled nbhd tile
    float* cuS    = nbS    + NEDGE*CC;        // [16][256] center@(Ud|Ur)
    float* biasS  = cuS    + TILE_P*256;      // [9][256]
    float* cenS   = biasS  + NBR*256;         // [16][128] centers (reused as wsS)
    float* driveS = cenS   + TILE_P*CC;       // [144]
    float* resS   = driveS + NEDGE;           // [144]
    float* gateS  = resS   + NEDGE;           // [144]
    float* invmS  = gateS  + NEDGE;           // [16]
    float* sgS    = invmS  + TILE_P;          // [16]
    float* wsS  = cenS;    // reuse (cen dead after cu phase)
    float* msgS = cuS;     // reuse (cu dead after GEMM)
    float* uS   = nbS;     // reuse (nb dead after weighted sum)

    const int tid = threadIdx.x;
    const int blk = blockIdx.x;
    const int b   = blk >> 10;
    const int t   = blk & 1023;
    const int h   = t >> 3;
    const int w0  = (t & 7) << 4;
    const int rowbase = (b*HH + h)*WW + w0;   // flat position index of p=0
    const int lane = tid & 31;

    // --- stage bias table [9][256] ---
    for (int idx = tid; idx < NBR*256; idx += NTHREADS) {
        int n = idx >> 8, j = idx & 255;
        biasS[idx] = (j < 128) ? g_biasd[n*CC + j] : g_biasr[n*CC + j - 128];
    }
    // --- stage centers [16][128] ---
    for (int idx = tid; idx < TILE_P*CC; idx += NTHREADS)
        cenS[idx] = g_norm[(long)rowbase*CC + idx];
    // --- gather scrambled nbhd, SOURCE-MAJOR iteration for coalesced loads ---
    // nbhd[p,n,c] = padnorm[shift s][c2] with f = n*128+c = c2*9+s.
    // Iterate idx = (p, s, c2): loads are contiguous c2 runs; stores stride-9 (bank-free).
    for (int idx = tid; idx < TILE_P*NBR*CC; idx += NTHREADS) {
        int p  = idx / 1152;              // 1152 = 9*128
        int r  = idx - p*1152;
        int s  = r >> 7;                  // shift index 0..8
        int c2 = r & 127;                 // source channel
        int f  = c2*9 + s;
        int n  = f >> 7;
        int c  = f & 127;
        int di = s / 3;
        int dj = s - di*3;
        int hh = h + di - 1;
        int ww = w0 + p + dj - 1;
        float val = 0.0f;
        if ((unsigned)hh < HH && (unsigned)ww < WW)
            val = g_norm[(((long)(b*HH + hh)*WW + ww))*CC + c2];
        nbS[(p*9 + n)*CC + c] = val;
    }
    __syncthreads();

    // --- cu = center @ [Ud|Ur]: warp = 32-j block, thread accumulates all 16 p ---
    {
        const int wj = (tid >> 5) << 5;             // warp's j base (0..224)
        const int j  = wj + lane;                   // 0..255
        const float* Up = (j < 128) ? (g_Ud + j) : (g_Ur + j - 128);
        float acc[TILE_P];
        #pragma unroll
        for (int p = 0; p < TILE_P; ++p) acc[p] = 0.0f;
        for (int c0 = 0; c0 < CC; c0 += 4) {
            float4 cq[TILE_P];
            #pragma unroll
            for (int p = 0; p < TILE_P; ++p)
                cq[p] = *reinterpret_cast<const float4*>(cenS + p*CC + c0);
            #pragma unroll
            for (int cc = 0; cc < 4; ++cc) {
                float u = Up[(c0 + cc)*CC];         // coalesced 128B per warp
                #pragma unroll
                for (int p = 0; p < TILE_P; ++p) {
                    float cv = (cc == 0) ? cq[p].x : (cc == 1) ? cq[p].y
                             : (cc == 2) ? cq[p].z : cq[p].w;
                    acc[p] = fmaf(cv, u, acc[p]);
                }
            }
        }
        #pragma unroll
        for (int p = 0; p < TILE_P; ++p)
            cuS[p*256 + j] = acc[p];
    }
    __syncthreads();

    // --- edge GEMM: thread (ty,tx) = position ty, j-octet tx; 2 passes (drive/res) ---
    {
        const int ty = tid >> 4;                   // position 0..15
        const int tx = tid & 15;                   // j-octet 0..15
        const float* nbp = nbS + ty*9*CC;
        #pragma unroll
        for (int pass = 0; pass < 2; ++pass) {
            const float* Vp  = ((pass == 0) ? g_Vd : g_Vr) + tx*8;
            const float* W2p = ((pass == 0) ? dW2  : rW2)  + tx*8;
            float w2[8];
            #pragma unroll
            for (int q = 0; q < 8; ++q) w2[q] = W2p[q];

            float2 acc[9][4];
            {
                const float* cub = cuS + ty*256 + pass*128 + tx*8;
                float4 cu0 = *reinterpret_cast<const float4*>(cub);
                float4 cu1 = *reinterpret_cast<const float4*>(cub + 4);
                #pragma unroll
                for (int i = 0; i < 9; ++i) {
                    const float* bb = biasS + i*256 + pass*128 + tx*8;
                    float4 b0 = *reinterpret_cast<const float4*>(bb);
                    float4 b1 = *reinterpret_cast<const float4*>(bb + 4);
                    acc[i][0] = make_float2(cu0.x + b0.x, cu0.y + b0.y);
                    acc[i][1] = make_float2(cu0.z + b0.z, cu0.w + b0.w);
                    acc[i][2] = make_float2(cu1.x + b1.x, cu1.y + b1.y);
                    acc[i][3] = make_float2(cu1.z + b1.z, cu1.w + b1.w);
                }
            }
            #pragma unroll 2
            for (int c0 = 0; c0 < CC; c0 += 2) {
                float2 nbq[9];
                #pragma unroll
                for (int i = 0; i < 9; ++i)
                    nbq[i] = *reinterpret_cast<const float2*>(nbp + i*CC + c0);
                #pragma unroll
                for (int cc = 0; cc < 2; ++cc) {
                    const float* vr = Vp + (c0 + cc)*CC;
                    float4 v0 = *reinterpret_cast<const float4*>(vr);
                    float4 v1 = *reinterpret_cast<const float4*>(vr + 4);
                    float2 vA = make_float2(v0.x, v0.y);
                    float2 vB = make_float2(v0.z, v0.w);
                    float2 vC = make_float2(v1.x, v1.y);
                    float2 vD = make_float2(v1.z, v1.w);
                    #pragma unroll
                    for (int i = 0; i < 9; ++i) {
                        float nbv = cc ? nbq[i].y : nbq[i].x;
                        float2 nb2 = make_float2(nbv, nbv);
                        acc[i][0] = ffma2(nb2, vA, acc[i][0]);
                        acc[i][1] = ffma2(nb2, vB, acc[i][1]);
                        acc[i][2] = ffma2(nb2, vC, acc[i][2]);
                        acc[i][3] = ffma2(nb2, vD, acc[i][3]);
                    }
                }
            }
            #pragma unroll
            for (int i = 0; i < 9; ++i) {
                float s = gelu_exact(acc[i][0].x)*w2[0] + gelu_exact(acc[i][0].y)*w2[1]
                        + gelu_exact(acc[i][1].x)*w2[2] + gelu_exact(acc[i][1].y)*w2[3]
                        + gelu_exact(acc[i][2].x)*w2[4] + gelu_exact(acc[i][2].y)*w2[5]
                        + gelu_exact(acc[i][3].x)*w2[6] + gelu_exact(acc[i][3].y)*w2[7];
                #pragma unroll
                for (int o = 8; o; o >>= 1)
                    s += __shfl_xor_sync(0xffffffffu, s, o);
                if (tx == 0)
                    ((pass == 0) ? driveS : resS)[ty*9 + i] = s;
            }
        }
    }
    __syncthreads();

    // --- EML gate ---
    const float gamma = *p_gamma, lam = *p_lam, ebias = *p_bias;
    if (tid < NEDGE) {
        float d = driveS[tid] + db2[0];
        float r = resS[tid]   + rb2[0];
        float sp = fmaxf(r, 0.0f) + log1pf(expf(-fabsf(r)));   // jax softplus
        float en = gamma * d / (lam * sp + 1e-6f) + ebias;
        en = fminf(fmaxf(en, -3.0f), 3.0f);
        gateS[tid] = 1.0f / (1.0f + expf(-en));
    }
    __syncthreads();
    if (tid < TILE_P) {
        float s = 0.0f;
        #pragma unroll
        for (int n = 0; n < 9; ++n) s += gateS[tid*9 + n];
        sgS[tid]   = s;
        invmS[tid] = 1.0f / fmaxf(s, 1e-6f);
    }
    __syncthreads();

    // --- ws[p][c] = (sum_n gate*nbhd)/mass ---
    {
        int p = tid >> 4, cg = tid & 15;
        float im = invmS[p];
        float gr[9];
        #pragma unroll
        for (int n = 0; n < 9; ++n) gr[n] = gateS[p*9 + n];
        #pragma unroll
        for (int k = 0; k < 8; ++k) {
            int c = cg + (k << 4);
            float s = 0.0f;
            #pragma unroll
            for (int n = 0; n < 9; ++n) s += gr[n] * nbS[(p*9 + n)*CC + c];
            wsS[p*CC + c] = s * im;
        }
    }
    __syncthreads();

    // --- message = ws @ vW + vb*(sum_gate/mass)   (c-outer, contiguous d, packed) ---
    {
        int p = tid >> 4, dg = tid & 15;
        int d0 = dg * 8;                        // thread owns d in [d0, d0+8)
        float coef = sgS[p] * invmS[p];
        float2 acc[4] = {{0,0},{0,0},{0,0},{0,0}};
        const float* wsp = wsS + p*CC;
        #pragma unroll 4
        for (int c = 0; c < CC; ++c) {
            float w = wsp[c];                   // broadcast LDS
            float2 w2 = make_float2(w, w);
            const float4* vr = reinterpret_cast<const float4*>(vW + c*CC + d0);
            float4 v0 = vr[0], v1 = vr[1];
            acc[0] = ffma2(w2, make_float2(v0.x, v0.y), acc[0]);
            acc[1] = ffma2(w2, make_float2(v0.z, v0.w), acc[1]);
            acc[2] = ffma2(w2, make_float2(v1.x, v1.y), acc[2]);
            acc[3] = ffma2(w2, make_float2(v1.z, v1.w), acc[3]);
        }
        #pragma unroll
        for (int k = 0; k < 4; ++k) {
            msgS[p*CC + d0 + 2*k]     = acc[k].x + vb[d0 + 2*k]     * coef;
            msgS[p*CC + d0 + 2*k + 1] = acc[k].y + vb[d0 + 2*k + 1] * coef;
        }
    }
    __syncthreads();

    // --- u = tokens + message @ oW + ob   (same structure) ---
    {
        int p = tid >> 4, dg = tid & 15;
        int d0 = dg * 8;
        long grow = (long)(rowbase + p) * CC;
        float2 acc[4] = {{0,0},{0,0},{0,0},{0,0}};
        const float* mp = msgS + p*CC;
        #pragma unroll 4
        for (int c = 0; c < CC; ++c) {
            float w = mp[c];
            float2 w2 = make_float2(w, w);
            const float4* orr = reinterpret_cast<const float4*>(oW + c*CC + d0);
            float4 v0 = orr[0], v1 = orr[1];
            acc[0] = ffma2(w2, make_float2(v0.x, v0.y), acc[0]);
            acc[1] = ffma2(w2, make_float2(v0.z, v0.w), acc[1]);
            acc[2] = ffma2(w2, make_float2(v1.x, v1.y), acc[2]);
            acc[3] = ffma2(w2, make_float2(v1.z, v1.w), acc[3]);
        }
        __syncthreads();   // msgS reads done before uS (aliases nbS) writes
        #pragma unroll
        for (int k = 0; k < 4; ++k) {
            int d2 = d0 + 2*k;
            uS[p*CC + d2]     = tokens[grow + d2]     + acc[k].x + ob[d2];
            uS[p*CC + d2 + 1] = tokens[grow + d2 + 1] + acc[k].y + ob[d2 + 1];
        }
    }
    __syncthreads();

    // --- LN2 + store ---
    {
        int warp = tid >> 5, lanei = tid & 31;
        #pragma unroll
        for (int pp = 0; pp < 2; ++pp) {
            int p = warp*2 + pp;
            float4 x = reinterpret_cast<const float4*>(uS + p*CC)[lanei];
            float s = x.x + x.y + x.z + x.w;
            #pragma unroll
            for (int o = 16; o; o >>= 1) s += __shfl_xor_sync(0xffffffffu, s, o);
            float m = s * (1.0f/128.0f);
            float dx = x.x - m, dy = x.y - m, dz = x.z - m, dw = x.w - m;
            float v = dx*dx + dy*dy + dz*dz + dw*dw;
            #pragma unroll
            for (int o = 16; o; o >>= 1) v += __shfl_xor_sync(0xffffffffu, v, o);
            float rs = rsqrtf(v * (1.0f/128.0f) + 1e-5f);
            int c = lanei * 4;
            float4 o4;
            o4.x = dx*rs*ln2_g[c+0] + ln2_b[c+0];
            o4.y = dy*rs*ln2_g[c+1] + ln2_b[c+1];
            o4.z = dz*rs*ln2_g[c+2] + ln2_b[c+2];
            o4.w = dw*rs*ln2_g[c+3] + ln2_b[c+3];
            reinterpret_cast<float4*>(out + (long)(rowbase + p)*CC)[lanei] = o4;
        }
    }
}

// ---------------- launch ----------------
extern "C" void kernel_launch(void* const* d_in, const int* in_sizes, int n_in,
                              void* d_out, int out_size) {
    const float* tokens = (const float*)d_in[0];
    const float* ln1_g  = (const float*)d_in[1];
    const float* ln1_b  = (const float*)d_in[2];
    const float* ln2_g  = (const float*)d_in[3];
    const float* ln2_b  = (const float*)d_in[4];
    const float* rel_pos= (const float*)d_in[5];
    const float* dW1    = (const float*)d_in[6];
    const float* db1    = (const float*)d_in[7];
    const float* dW2    = (const float*)d_in[8];
    const float* db2    = (const float*)d_in[9];
    const float* rW1    = (const float*)d_in[10];
    const float* rb1    = (const float*)d_in[11];
    const float* rW2    = (const float*)d_in[12];
    const float* rb2    = (const float*)d_in[13];
    const float* vW     = (const float*)d_in[14];
    const float* vb     = (const float*)d_in[15];
    const float* oW     = (const float*)d_in[16];
    const float* ob     = (const float*)d_in[17];
    const float* gamma  = (const float*)d_in[18];
    const float* lam    = (const float*)d_in[19];
    const float* ebias  = (const float*)d_in[20];
    float* out = (float*)d_out;

    const int SMEM = (NEDGE*CC + TILE_P*256 + NBR*256 + TILE_P*CC + NEDGE*3 + TILE_P*2) * 4;

    setup_kernel<<<4096 + 64, 256>>>(tokens, ln1_g, ln1_b, dW1, db1, rW1, rb1, rel_pos);
    cudaFuncSetAttribute(eml_main_kernel, cudaFuncAttributeMaxDynamicSharedMemorySize, SMEM);
    eml_main_kernel<<<(BB*HH*WW)/TILE_P, 256, SMEM>>>(tokens, ln2_g, ln2_b, dW2, db2,
                                                      rW2, rb2, vW, vb, oW, ob,
                                                      gamma, lam, ebias, out);
}